// round 15
// baseline (speedup 1.0000x reference)
#include <cuda_runtime.h>
#include <math.h>
#include <stdint.h>

#define NN 20000
#define NE 320000
#define NG 64

// ---- scratch (device globals; no allocation allowed) ----
__device__ __align__(16) float g_h  [NN * 256];
__device__ __align__(16) float g_agg[NN * 256];
__device__ __align__(16) float g_t  [NN * 256];
__device__ __align__(16) float g_pool[NG * 256];
__device__ float g_cnt[NG];
__device__ __align__(16) int g_histo[NN];
__device__ __align__(16) int g_perm[NE];
// pre-split, pre-permuted edge_attr: per physical row q, 64 words in 4 k16
// blocks; block s (16 k values) = [8 hi pairs | 8 lo pairs] at words [16s,16s+16)
__device__ __align__(16) uint32_t g_eabf[NE * 64];

// ---------------- PTX helpers ----------------
__device__ __forceinline__ void splitv(float2 v, uint32_t& h, uint32_t& l) {
    asm("cvt.rn.bf16x2.f32 %0, %1, %2;" : "=r"(h) : "f"(v.y), "f"(v.x));
    float f0 = __uint_as_float(h << 16);
    float f1 = __uint_as_float(h & 0xFFFF0000u);
    asm("cvt.rn.bf16x2.f32 %0, %1, %2;" : "=r"(l) : "f"(v.y - f1), "f"(v.x - f0));
}

__device__ __forceinline__ void mma16(float* d, const uint32_t* a, const uint32_t* b) {
    asm volatile(
        "mma.sync.aligned.m16n8k16.row.col.f32.bf16.bf16.f32 "
        "{%0,%1,%2,%3}, {%4,%5,%6,%7}, {%8,%9}, {%0,%1,%2,%3};"
        : "+f"(d[0]), "+f"(d[1]), "+f"(d[2]), "+f"(d[3])
        : "r"(a[0]), "r"(a[1]), "r"(a[2]), "r"(a[3]), "r"(b[0]), "r"(b[1]));
}

__device__ __forceinline__ void cp16(uint32_t saddr, const void* gptr) {
    asm volatile("cp.async.cg.shared.global [%0], [%1], 16;" :: "r"(saddr), "l"(gptr));
}
__device__ __forceinline__ void cp_commit() { asm volatile("cp.async.commit_group;"); }

__device__ __forceinline__ void red_add_v4(float* addr, float4 v) {
    asm volatile("red.global.add.v4.f32 [%0], {%1,%2,%3,%4};"
                 :: "l"(addr), "f"(v.x), "f"(v.y), "f"(v.z), "f"(v.w) : "memory");
}

__global__ void zero4(float4* p, int n4) {
    int i = blockIdx.x * blockDim.x + threadIdx.x;
    if (i < n4) p[i] = make_float4(0.f, 0.f, 0.f, 0.f);
}

// ---------------- counting sort of edges by dst ----------------
__global__ void hist_kernel(const int* __restrict__ ei, int* __restrict__ histo) {
    int e = blockIdx.x * blockDim.x + threadIdx.x;
    if (e < NE) atomicAdd(&histo[ei[NE + e]], 1);
}

__global__ void scan_kernel(int* __restrict__ histo) {
    __shared__ int s[1024];
    const int t = threadIdx.x;
    const int CH = (NN + 1023) / 1024;   // 20
    const int base = t * CH;
    int sum = 0;
    #pragma unroll
    for (int i = 0; i < CH; i++) {
        int idx = base + i;
        if (idx < NN) sum += histo[idx];
    }
    s[t] = sum;
    __syncthreads();
    for (int d = 1; d < 1024; d <<= 1) {
        int add = (t >= d) ? s[t - d] : 0;
        __syncthreads();
        s[t] += add;
        __syncthreads();
    }
    int run = s[t] - sum;
    #pragma unroll
    for (int i = 0; i < CH; i++) {
        int idx = base + i;
        if (idx < NN) {
            int c = histo[idx];
            histo[idx] = run;
            run += c;
        }
    }
}

__global__ void scatter_kernel(const int* __restrict__ ei,
                               int* __restrict__ histo, int* __restrict__ perm) {
    int e = blockIdx.x * blockDim.x + threadIdx.x;
    if (e < NE) {
        int pos = atomicAdd(&histo[ei[NE + e]], 1);
        perm[pos] = e;
    }
}

// Pre-split + pre-permute edge_attr. Thread -> one k-pair of one physical row.
// Physical row q hosts sorted edge (q & ~127) + el(q & 127).
// Word layout per row: k16 block s at words [16s, 16s+16): 8 hi then 8 lo.
__global__ void presplit_ea(const float* __restrict__ ea,
                            const int* __restrict__ perm,
                            uint32_t* __restrict__ out)
{
    long long idx = (long long)blockIdx.x * blockDim.x + threadIdx.x;  // NE*32
    if (idx >= (long long)NE * 32) return;
    int q = (int)(idx >> 5), kp = (int)(idx & 31);   // k-pair 0..31
    int m = q & 127;
    int el = (m & ~31) + 4 * (m & 7) + ((m >> 3) & 3);
    int pe = perm[(q & ~127) + el];
    float2 v = *(const float2*)(ea + (size_t)pe * 64 + 2 * kp);
    uint32_t hi, lo;
    splitv(v, hi, lo);
    int blk = kp >> 3, w = kp & 7;   // k16 block, pair within block
    out[(size_t)q * 64 + blk * 16 + w]     = hi;
    out[(size_t)q * 64 + blk * 16 + 8 + w] = lo;
}

// ---- smem strides ----
#define AST 20     // node A: [rows][16 k floats] stride 20 floats
#define EAW 68     // edge A: [rows][64 words] stride 68 (68%32==4 -> bank 4g+tig)
#define BST 140    // B: [16 k][128 n] stride 140
#define HST 136    // H: [128 rows][128 cols] stride 136

// dynamic smem layout for edge kernel (words)
#define EOFF_B0 (128 * EAW)
#define EOFF_B1 (128 * EAW + 16 * BST)
#define EOFF_H  (128 * EAW + 2 * 16 * BST)
#define ESMEM_WORDS (EOFF_H + 128 * HST)
#define ESMEM_BYTES (ESMEM_WORDS * 4)   // (8704+4480+17408)*4 = 122368? see note

// NOTE: 128*68=8704, 2*16*140=4480, 128*136=17408 -> 30592 words = 122368 B.
// Too big for 2 CTAs/SM (228KB/SM): 2x122368=244KB. Drop H stride to 132 and
// EAW already minimal -> instead store H as the limiting factor; accept 1 CTA/SM
// fallback is a risk, so shrink: use HST 132 (16B-quad period 33, conflict-free
// quads) and B single-buffered? Keep it simple: HST 132 saves 2KB only.
// Decision: accept ESMEM as-is; occupancy 1 CTA/SM risk noted in theory.

// ---------------------------------------------------------------------------
// Node GEMM (unchanged from R13/R14).
// ---------------------------------------------------------------------------
template<bool RELU, bool DUAL>
__global__ __launch_bounds__(256, 2)
void mma_gemm(const float* __restrict__ A, const float* __restrict__ W,
              const float* __restrict__ bias, float* __restrict__ C,
              float* __restrict__ C2, int M, int K)
{
    __shared__ float As[2][128 * AST];
    __shared__ float Bs[2][16 * BST];

    const int tid  = threadIdx.x;
    const int lane = tid & 31;
    const int wid  = tid >> 5;
    const int g    = lane >> 2;
    const int tig  = lane & 3;
    const int wm   = wid & 3;
    const int wn   = wid >> 2;
    const int rowTile = blockIdx.y * 128;
    const int colTile = blockIdx.x * 128;

    float acc[2][8][4];
    #pragma unroll
    for (int mt = 0; mt < 2; mt++)
        #pragma unroll
        for (int nt = 0; nt < 8; nt++)
            #pragma unroll
            for (int j = 0; j < 4; j++) acc[mt][nt][j] = 0.f;

    const int S = K >> 4;

    uint32_t ab[2], bb[2];
    ab[0] = (uint32_t)__cvta_generic_to_shared(&As[0][0]);
    ab[1] = (uint32_t)__cvta_generic_to_shared(&As[1][0]);
    bb[0] = (uint32_t)__cvta_generic_to_shared(&Bs[0][0]);
    bb[1] = (uint32_t)__cvta_generic_to_shared(&Bs[1][0]);

    auto stage = [&](int k0, uint32_t abase, uint32_t bbase) {
        #pragma unroll
        for (int i = 0; i < 2; i++) {
            int slot = tid + (i << 8);
            int m = slot >> 2, seg = slot & 3;
            int gr = rowTile + m; if (gr >= M) gr = M - 1;
            cp16(abase + (uint32_t)(m * AST + seg * 4) * 4,
                 A + (size_t)gr * K + k0 + seg * 4);
        }
        #pragma unroll
        for (int i = 0; i < 2; i++) {
            int slot = tid + (i << 8);
            int k = slot >> 5, seg = slot & 31;
            cp16(bbase + (uint32_t)(k * BST + seg * 4) * 4,
                 W + (size_t)(k0 + k) * 256 + colTile + seg * 4);
        }
    };

    stage(0, ab[0], bb[0]);
    cp_commit();

    for (int s = 0; s < S; s++) {
        const int buf = s & 1;
        if (s + 1 < S) {
            stage((s + 1) << 4, ab[buf ^ 1], bb[buf ^ 1]);
            cp_commit();
            asm volatile("cp.async.wait_group 1;");
        } else {
            asm volatile("cp.async.wait_group 0;");
        }
        __syncthreads();

        const float* as = As[buf];
        const float* bs = Bs[buf];

        uint32_t ah[2][4], al[2][4];
        #pragma unroll
        for (int mt = 0; mt < 2; mt++) {
            const int m0 = wm * 32 + mt * 16 + g;
            const int m1 = m0 + 8;
            splitv(*(const float2*)&as[m0 * AST + 2 * tig],     ah[mt][0], al[mt][0]);
            splitv(*(const float2*)&as[m1 * AST + 2 * tig],     ah[mt][1], al[mt][1]);
            splitv(*(const float2*)&as[m0 * AST + 2 * tig + 8], ah[mt][2], al[mt][2]);
            splitv(*(const float2*)&as[m1 * AST + 2 * tig + 8], ah[mt][3], al[mt][3]);
        }

        #pragma unroll
        for (int half = 0; half < 2; half++) {
            uint32_t bh[4][2], bl[4][2];
            #pragma unroll
            for (int q = 0; q < 4; q++) {
                const int n = wn * 64 + (half * 4 + q) * 8 + g;
                float2 v0, v1;
                v0.x = bs[(2 * tig)     * BST + n];
                v0.y = bs[(2 * tig + 1) * BST + n];
                v1.x = bs[(2 * tig + 8) * BST + n];
                v1.y = bs[(2 * tig + 9) * BST + n];
                splitv(v0, bh[q][0], bl[q][0]);
                splitv(v1, bh[q][1], bl[q][1]);
            }
            #pragma unroll
            for (int mt = 0; mt < 2; mt++)
                #pragma unroll
                for (int q = 0; q < 4; q++) {
                    const int nt = half * 4 + q;
                    mma16(acc[mt][nt], ah[mt], bh[q]);
                    mma16(acc[mt][nt], ah[mt], bl[q]);
                    mma16(acc[mt][nt], al[mt], bh[q]);
                }
        }
        __syncthreads();
    }

    #pragma unroll
    for (int mt = 0; mt < 2; mt++) {
        const int r0 = rowTile + wm * 32 + mt * 16 + g;
        const int r1 = r0 + 8;
        #pragma unroll
        for (int nt = 0; nt < 8; nt++) {
            const int col = colTile + wn * 64 + nt * 8 + tig * 2;
            float2 bv = *(const float2*)(bias + col);
            if (r0 < M) {
                float2 v;
                v.x = acc[mt][nt][0] + bv.x;
                v.y = acc[mt][nt][1] + bv.y;
                if (RELU) { v.x = fmaxf(v.x, 0.f); v.y = fmaxf(v.y, 0.f); }
                *(float2*)(C + (size_t)r0 * 256 + col) = v;
                if (DUAL) *(float2*)(C2 + (size_t)r0 * 256 + col) = v;
            }
            if (r1 < M) {
                float2 v;
                v.x = acc[mt][nt][2] + bv.x;
                v.y = acc[mt][nt][3] + bv.y;
                if (RELU) { v.x = fmaxf(v.x, 0.f); v.y = fmaxf(v.y, 0.f); }
                *(float2*)(C + (size_t)r1 * 256 + col) = v;
                if (DUAL) *(float2*)(C2 + (size_t)r1 * 256 + col) = v;
            }
        }
    }
}

// ---------------------------------------------------------------------------
// Edge-fused GEMM on dst-sorted edges. CTA tile 128 edges x 128 cols, K=64.
// A = pre-split pre-permuted bf16 (g_eabf, whole K resident in smem, loaded
// once, sequentially). Zero A conversions in the mainloop. H prefetched.
// ---------------------------------------------------------------------------
__global__ __launch_bounds__(256, 2)
void edge_gemm(const uint32_t* __restrict__ Abf, const float* __restrict__ W,
               const float* __restrict__ bias,
               const int* __restrict__ ei, const int* __restrict__ perm,
               const float* __restrict__ hg, float* __restrict__ agg)
{
    extern __shared__ uint32_t esm[];
    uint32_t* Aw = esm;                                  // [128][EAW]
    float* Bs[2] = { (float*)(esm + EOFF_B0), (float*)(esm + EOFF_B1) };
    float* Hs    = (float*)(esm + EOFF_H);
    __shared__ int src_s[128];
    __shared__ int dst_s[128];

    const int tid  = threadIdx.x;
    const int lane = tid & 31;
    const int wid  = tid >> 5;
    const int g    = lane >> 2;
    const int tig  = lane & 3;
    const int wm   = wid & 3;
    const int wn   = wid >> 2;
    const int rowTile = blockIdx.y * 128;
    const int colTile = blockIdx.x * 128;

    if (tid < 128) {
        int pe = perm[rowTile + tid];
        src_s[tid] = ei[pe];
        dst_s[tid] = ei[NE + pe];
    }
    __syncthreads();

    float acc[2][8][4];
    #pragma unroll
    for (int mt = 0; mt < 2; mt++)
        #pragma unroll
        for (int nt = 0; nt < 8; nt++)
            #pragma unroll
            for (int j = 0; j < 4; j++) acc[mt][nt][j] = 0.f;

    uint32_t abase = (uint32_t)__cvta_generic_to_shared(Aw);
    uint32_t bb[2], hbase;
    bb[0] = (uint32_t)__cvta_generic_to_shared(Bs[0]);
    bb[1] = (uint32_t)__cvta_generic_to_shared(Bs[1]);
    hbase = (uint32_t)__cvta_generic_to_shared(Hs);

    auto stage_b = [&](int k0, uint32_t bbase) {
        #pragma unroll
        for (int i = 0; i < 2; i++) {
            int slot = tid + (i << 8);
            int k = slot >> 5, seg = slot & 31;
            cp16(bbase + (uint32_t)(k * BST + seg * 4) * 4,
                 W + (size_t)(k0 + k) * 256 + colTile + seg * 4);
        }
    };

    // G0: whole A tile (128 rows x 64 words = 2048 x 16B chunks, 8/thread;
    // fully sequential global reads) + B stage 0
    #pragma unroll
    for (int i = 0; i < 8; i++) {
        int slot = tid + (i << 8);
        int m = slot >> 4, seg = slot & 15;
        cp16(abase + (uint32_t)(m * EAW + seg * 4) * 4,
             Abf + (size_t)(rowTile + m) * 64 + seg * 4);
    }
    stage_b(0, bb[0]);
    cp_commit();

    // G1: H prefetch — 128 rows x 128 cols fp32 = 4096 x 16B chunks, 16/thread.
    #pragma unroll
    for (int i = 0; i < 16; i++) {
        int c2 = tid + (i << 8);
        int p = c2 >> 5, cseg = c2 & 31;
        int el = (p & ~31) + 4 * (p & 7) + ((p >> 3) & 3);
        int src = src_s[el];
        cp16(hbase + (uint32_t)(p * HST + cseg * 4) * 4,
             hg + (size_t)src * 256 + colTile + cseg * 4);
    }
    cp_commit();

    #pragma unroll
    for (int s = 0; s < 4; s++) {   // K = 64 -> 4 k16 stages (B double-buffered)
        const int buf = s & 1;
        if (s + 1 < 4) {
            stage_b((s + 1) << 4, bb[buf ^ 1]);
            cp_commit();
        }
        if (s == 0)      asm volatile("cp.async.wait_group 2;");
        else if (s < 3)  asm volatile("cp.async.wait_group 1;");
        else             asm volatile("cp.async.wait_group 0;");
        __syncthreads();

        const float* bs = Bs[buf];
        const int kb = s * 16;   // word offset of this k16 block

        uint32_t ah[2][4], al[2][4];
        #pragma unroll
        for (int mt = 0; mt < 2; mt++) {
            const int m0 = wm * 32 + mt * 16 + g;
            const int m1 = m0 + 8;
            const uint32_t* r0 = Aw + m0 * EAW + kb;
            const uint32_t* r1 = Aw + m1 * EAW + kb;
            ah[mt][0] = r0[tig];         ah[mt][1] = r1[tig];
            ah[mt][2] = r0[tig + 4];     ah[mt][3] = r1[tig + 4];
            al[mt][0] = r0[8 + tig];     al[mt][1] = r1[8 + tig];
            al[mt][2] = r0[8 + tig + 4]; al[mt][3] = r1[8 + tig + 4];
        }

        #pragma unroll
        for (int half = 0; half < 2; half++) {
            uint32_t bh[4][2], bl[4][2];
            #pragma unroll
            for (int q = 0; q < 4; q++) {
                const int n = wn * 64 + (half * 4 + q) * 8 + g;
                float2 v0, v1;
                v0.x = bs[(2 * tig)     * BST + n];
                v0.y = bs[(2 * tig + 1) * BST + n];
                v1.x = bs[(2 * tig + 8) * BST + n];
                v1.y = bs[(2 * tig + 9) * BST + n];
                splitv(v0, bh[q][0], bl[q][0]);
                splitv(v1, bh[q][1], bl[q][1]);
            }
            #pragma unroll
            for (int mt = 0; mt < 2; mt++)
                #pragma unroll
                for (int q = 0; q < 4; q++) {
                    const int nt = half * 4 + q;
                    mma16(acc[mt][nt], ah[mt], bh[q]);
                    mma16(acc[mt][nt], ah[mt], bl[q]);
                    mma16(acc[mt][nt], al[mt], bh[q]);
                }
        }
        if (s + 1 < 4) __syncthreads();
    }

    // ---- fused epilogue: smem h + relu + run-combined scatter ----
    const int eb = wm * 32 + 4 * g;
    const int d0 = dst_s[eb + 0], d1 = dst_s[eb + 1];
    const int d2 = dst_s[eb + 2], d3 = dst_s[eb + 3];
    const int hrow = wm * 32 + g;
    const bool even = (tig & 1) == 0;

    #pragma unroll
    for (int nt = 0; nt < 8; nt++) {
        float p[2][4];
        #pragma unroll
        for (int mt = 0; mt < 2; mt++)
            #pragma unroll
            for (int j = 0; j < 4; j++)
                p[mt][j] = __shfl_xor_sync(0xffffffffu, acc[mt][nt][j], 1);

        if (even) {
            const int lcol = wn * 64 + nt * 8 + tig * 2;
            const int col = colTile + lcol;
            float4 bv = *(const float4*)(bias + col);
            float4 v0, v1, v2, v3;
            v0.x = acc[0][nt][0] + bv.x; v0.y = acc[0][nt][1] + bv.y;
            v0.z = p[0][0] + bv.z;       v0.w = p[0][1] + bv.w;
            v1.x = acc[0][nt][2] + bv.x; v1.y = acc[0][nt][3] + bv.y;
            v1.z = p[0][2] + bv.z;       v1.w = p[0][3] + bv.w;
            v2.x = acc[1][nt][0] + bv.x; v2.y = acc[1][nt][1] + bv.y;
            v2.z = p[1][0] + bv.z;       v2.w = p[1][1] + bv.w;
            v3.x = acc[1][nt][2] + bv.x; v3.y = acc[1][nt][3] + bv.y;
            v3.z = p[1][2] + bv.z;       v3.w = p[1][3] + bv.w;

            float4 h0 = *(const float4*)(Hs + (hrow +  0) * HST + lcol);
            float4 h1 = *(const float4*)(Hs + (hrow +  8) * HST + lcol);
            float4 h2 = *(const float4*)(Hs + (hrow + 16) * HST + lcol);
            float4 h3 = *(const float4*)(Hs + (hrow + 24) * HST + lcol);

            v0.x = fmaxf(v0.x + h0.x, 0.f); v0.y = fmaxf(v0.y + h0.y, 0.f);
            v0.z = fmaxf(v0.z + h0.z, 0.f); v0.w = fmaxf(v0.w + h0.w, 0.f);
            v1.x = fmaxf(v1.x + h1.x, 0.f); v1.y = fmaxf(v1.y + h1.y, 0.f);
            v1.z = fmaxf(v1.z + h1.z, 0.f); v1.w = fmaxf(v1.w + h1.w, 0.f);
            v2.x = fmaxf(v2.x + h2.x, 0.f); v2.y = fmaxf(v2.y + h2.y, 0.f);
            v2.z = fmaxf(v2.z + h2.z, 0.f); v2.w = fmaxf(v2.w + h2.w, 0.f);
            v3.x = fmaxf(v3.x + h3.x, 0.f); v3.y = fmaxf(v3.y + h3.y, 0.f);
            v3.z = fmaxf(v3.z + h3.z, 0.f); v3.w = fmaxf(v3.w + h3.w, 0.f);

            float4 cur = v0; int cd = d0;
            if (d1 == cd) {
                cur.x += v1.x; cur.y += v1.y; cur.z += v1.z; cur.w += v1.w;
            } else {
                red_add_v4(agg + (size_t)cd * 256 + col, cur);
                cur = v1; cd = d1;
            }
            if (d2 == cd) {
                cur.x += v2.x; cur.y += v2.y; cur.z += v2.z; cur.w += v2.w;
            } else {
                red_add_v4(agg + (size_t)cd * 256 + col, cur);
                cur = v2; cd = d2;
            }
            if (d3 == cd) {
                cur.x += v3.x; cur.y += v3.y; cur.z += v3.z; cur.w += v3.w;
            } else {
                red_add_v4(agg + (size_t)cd * 256 + col, cur);
                cur = v3; cd = d3;
            }
            red_add_v4(agg + (size_t)cd * 256 + col, cur);
        }
    }
}

// One block (64 threads) per node: scatter mean-pool contributions.
__global__ void pool_kernel(const float* __restrict__ h,
                            const int* __restrict__ batch,
                            float* __restrict__ pool, float* __restrict__ cnt)
{
    const int node = blockIdx.x;
    const int gph = batch[node];
    const int t = threadIdx.x;
    float4 v = *reinterpret_cast<const float4*>(h + (size_t)node * 256 + t * 4);
    red_add_v4(pool + (size_t)gph * 256 + t * 4, v);
    if (t == 0) atomicAdd(cnt + gph, 1.0f);
}

// One block per graph: mean -> relu(g@W1+b1)@W2+b2 -> L2 normalize.
__global__ void final_kernel(const float* __restrict__ pool,
                             const float* __restrict__ cnt,
                             const float* __restrict__ W1, const float* __restrict__ b1,
                             const float* __restrict__ W2, const float* __restrict__ b2,
                             float* __restrict__ out)
{
    const int gph = blockIdx.x;
    const int j = threadIdx.x;
    __shared__ float s[256];
    __shared__ float s2[256];
    __shared__ float redbuf[8];
    __shared__ float snorm;

    const float inv = 1.0f / fmaxf(cnt[gph], 1.0f);
    s[j] = pool[gph * 256 + j] * inv;
    __syncthreads();

    float t = b1[j];
    #pragma unroll 8
    for (int k = 0; k < 256; k++) t = fmaf(s[k], W1[k * 256 + j], t);
    t = fmaxf(t, 0.f);
    s2[j] = t;
    __syncthreads();

    float o = b2[j];
    #pragma unroll 8
    for (int k = 0; k < 256; k++) o = fmaf(s2[k], W2[k * 256 + j], o);

    float sq = o * o;
    #pragma unroll
    for (int off = 16; off > 0; off >>= 1)
        sq += __shfl_down_sync(0xffffffffu, sq, off);
    if ((j & 31) == 0) redbuf[j >> 5] = sq;
    __syncthreads();
    if (j == 0) {
        float ss = 0.f;
        #pragma unroll
        for (int w = 0; w < 8; w++) ss += redbuf[w];
        snorm = fmaxf(sqrtf(ss), 1e-12f);
    }
    __syncthreads();

    out[gph * 256 + j] = o / snorm;
}

extern "C" void kernel_launch(void* const* d_in, const int* in_sizes, int n_in,
                              void* d_out, int out_size)
{
    const float* x   = (const float*)d_in[0];
    const int*   ei  = (const int*)  d_in[1];
    const float* ea  = (const float*)d_in[2];
    const int*   bi  = (const int*)  d_in[3];
    const float* xW  = (const float*)d_in[4];
    const float* xb  = (const float*)d_in[5];
    const float* eW  = (const float*)d_in[6];
    const float* eb  = (const float*)d_in[7];
    const float* W1  = (const float*)d_in[8];
    const float* b1  = (const float*)d_in[9];
    const float* W2  = (const float*)d_in[10];
    const float* b2  = (const float*)d_in[11];
    const float* oW1 = (const float*)d_in[12];
    const float* ob1 = (const float*)d_in[13];
    const float* oW2 = (const float*)d_in[14];
    const float* ob2 = (const float*)d_in[15];
    float* out = (float*)d_out;

    float *ph, *pagg, *pt, *ppool, *pcnt;
    int *phisto, *pperm;
    uint32_t* peabf;
    cudaGetSymbolAddress((void**)&ph,    g_h);
    cudaGetSymbolAddress((void**)&pagg,  g_agg);
    cudaGetSymbolAddress((void**)&pt,    g_t);
    cudaGetSymbolAddress((void**)&ppool, g_pool);
    cudaGetSymbolAddress((void**)&pcnt,  g_cnt);
    cudaGetSymbolAddress((void**)&phisto, g_histo);
    cudaGetSymbolAddress((void**)&pperm,  g_perm);
    cudaGetSymbolAddress((void**)&peabf,  g_eabf);

    cudaFuncSetAttribute(edge_gemm,
                         cudaFuncAttributeMaxDynamicSharedMemorySize, ESMEM_BYTES);

    dim3 gNode(2, (NN + 127) / 128);   // (2, 157)
    dim3 gEdge(2, NE / 128);           // (2, 2500)

    // ---- counting sort of edges by dst ----
    zero4<<<(NN / 4 + 255) / 256, 256>>>((float4*)phisto, NN / 4);
    hist_kernel<<<(NE + 255) / 256, 256>>>(ei, phisto);
    scan_kernel<<<1, 1024>>>(phisto);
    scatter_kernel<<<(NE + 255) / 256, 256>>>(ei, phisto, pperm);

    // ---- pre-split + pre-permute edge_attr (reused by all 3 layers) ----
    presplit_ea<<<(int)(((long long)NE * 32 + 255) / 256), 256>>>(ea, pperm, peabf);

    // h = x @ xproj_W + xproj_b; agg = h (dual store)
    mma_gemm<false, true><<<gNode, 256>>>(x, xW, xb, ph, pagg, NN, 128);

    for (int l = 0; l < 3; l++) {
        edge_gemm<<<gEdge, 256, ESMEM_BYTES>>>(
            peabf, eW + l * 64 * 256, eb + l * 256, ei, pperm, ph, pagg);
        mma_gemm<true, false><<<gNode, 256>>>(
            pagg, W1 + l * 256 * 256, b1 + l * 256, pt, nullptr, NN, 256);
        if (l < 2)
            mma_gemm<true, true><<<gNode, 256>>>(
                pt, W2 + l * 256 * 256, b2 + l * 256, ph, pagg, NN, 256);
        else
            mma_gemm<true, false><<<gNode, 256>>>(
                pt, W2 + l * 256 * 256, b2 + l * 256, ph, nullptr, NN, 256);
    }

    // mean pool
    zero4<<<(NG * 64 + 255) / 256, 256>>>((float4*)ppool, NG * 64);
    zero4<<<1, 256>>>((float4*)pcnt, NG / 4);
    pool_kernel<<<NN, 64>>>(ph, bi, ppool, pcnt);

    // graph head + normalize
    final_kernel<<<NG, 256>>>(ppool, pcnt, oW1, ob1, oW2, ob2, out);
}

// round 16
// speedup vs baseline: 1.2500x; 1.2500x over previous
#include <cuda_runtime.h>
#include <math.h>
#include <stdint.h>

#define NN 20000
#define NE 320000
#define NG 64

// ---- scratch (device globals; no allocation allowed) ----
__device__ __align__(16) float g_h  [NN * 256];
__device__ __align__(16) float g_agg[NN * 256];
__device__ __align__(16) float g_t  [NN * 256];
__device__ __align__(16) float g_pool[NG * 256];
__device__ float g_cnt[NG];
__device__ __align__(16) int g_histo[NN];
__device__ __align__(16) int g_perm[NE];

// ---------------- PTX helpers ----------------
__device__ __forceinline__ void splitv(float2 v, uint32_t& h, uint32_t& l) {
    asm("cvt.rn.bf16x2.f32 %0, %1, %2;" : "=r"(h) : "f"(v.y), "f"(v.x));
    float f0 = __uint_as_float(h << 16);
    float f1 = __uint_as_float(h & 0xFFFF0000u);
    asm("cvt.rn.bf16x2.f32 %0, %1, %2;" : "=r"(l) : "f"(v.y - f1), "f"(v.x - f0));
}

__device__ __forceinline__ void mma16(float* d, const uint32_t* a, const uint32_t* b) {
    asm volatile(
        "mma.sync.aligned.m16n8k16.row.col.f32.bf16.bf16.f32 "
        "{%0,%1,%2,%3}, {%4,%5,%6,%7}, {%8,%9}, {%0,%1,%2,%3};"
        : "+f"(d[0]), "+f"(d[1]), "+f"(d[2]), "+f"(d[3])
        : "r"(a[0]), "r"(a[1]), "r"(a[2]), "r"(a[3]), "r"(b[0]), "r"(b[1]));
}

__device__ __forceinline__ void cp16(uint32_t saddr, const void* gptr) {
    asm volatile("cp.async.cg.shared.global [%0], [%1], 16;" :: "r"(saddr), "l"(gptr));
}
__device__ __forceinline__ void cp_commit() { asm volatile("cp.async.commit_group;"); }

__device__ __forceinline__ void red_add_v4(float* addr, float4 v) {
    asm volatile("red.global.add.v4.f32 [%0], {%1,%2,%3,%4};"
                 :: "l"(addr), "f"(v.x), "f"(v.y), "f"(v.z), "f"(v.w) : "memory");
}

__global__ void zero4(float4* p, int n4) {
    int i = blockIdx.x * blockDim.x + threadIdx.x;
    if (i < n4) p[i] = make_float4(0.f, 0.f, 0.f, 0.f);
}

// ---------------- counting sort of edges by dst ----------------
__global__ void hist_kernel(const int* __restrict__ ei, int* __restrict__ histo) {
    int e = blockIdx.x * blockDim.x + threadIdx.x;
    if (e < NE) atomicAdd(&histo[ei[NE + e]], 1);
}

__global__ void scan_kernel(int* __restrict__ histo) {
    __shared__ int s[1024];
    const int t = threadIdx.x;
    const int CH = (NN + 1023) / 1024;   // 20
    const int base = t * CH;
    int sum = 0;
    #pragma unroll
    for (int i = 0; i < CH; i++) {
        int idx = base + i;
        if (idx < NN) sum += histo[idx];
    }
    s[t] = sum;
    __syncthreads();
    for (int d = 1; d < 1024; d <<= 1) {
        int add = (t >= d) ? s[t - d] : 0;
        __syncthreads();
        s[t] += add;
        __syncthreads();
    }
    int run = s[t] - sum;
    #pragma unroll
    for (int i = 0; i < CH; i++) {
        int idx = base + i;
        if (idx < NN) {
            int c = histo[idx];
            histo[idx] = run;
            run += c;
        }
    }
}

__global__ void scatter_kernel(const int* __restrict__ ei,
                               int* __restrict__ histo, int* __restrict__ perm) {
    int e = blockIdx.x * blockDim.x + threadIdx.x;
    if (e < NE) {
        int pos = atomicAdd(&histo[ei[NE + e]], 1);
        perm[pos] = e;
    }
}

// ---- smem strides (floats) ----
#define AST 20     // A: [rows][16 k] stride 20
#define BST 140    // B: [16 k][128 n] stride 140
#define HST 136    // H: [128 rows][128 cols] stride 136

// dynamic smem layout for edge kernel (floats)
#define EOFF_A0 0
#define EOFF_A1 (128 * AST)
#define EOFF_B0 (2 * 128 * AST)
#define EOFF_B1 (2 * 128 * AST + 16 * BST)
#define EOFF_H  (2 * 128 * AST + 2 * 16 * BST)
#define ESMEM_FLOATS (EOFF_H + 128 * HST)
#define ESMEM_BYTES  (ESMEM_FLOATS * 4)     // 108032

// ---------------------------------------------------------------------------
// Node GEMM: CTA tile 128x128, warp tile 32x64, split-BF16 (3x m16n8k16),
// double buffered, K-step 16. Staging addresses hoisted out of the loop.
// ---------------------------------------------------------------------------
template<bool RELU, bool DUAL>
__global__ __launch_bounds__(256, 2)
void mma_gemm(const float* __restrict__ A, const float* __restrict__ W,
              const float* __restrict__ bias, float* __restrict__ C,
              float* __restrict__ C2, int M, int K)
{
    __shared__ float As[2][128 * AST];
    __shared__ float Bs[2][16 * BST];

    const int tid  = threadIdx.x;
    const int lane = tid & 31;
    const int wid  = tid >> 5;
    const int g    = lane >> 2;
    const int tig  = lane & 3;
    const int wm   = wid & 3;
    const int wn   = wid >> 2;
    const int rowTile = blockIdx.y * 128;
    const int colTile = blockIdx.x * 128;

    float acc[2][8][4];
    #pragma unroll
    for (int mt = 0; mt < 2; mt++)
        #pragma unroll
        for (int nt = 0; nt < 8; nt++)
            #pragma unroll
            for (int j = 0; j < 4; j++) acc[mt][nt][j] = 0.f;

    const int S = K >> 4;

    uint32_t ab[2], bb[2];
    ab[0] = (uint32_t)__cvta_generic_to_shared(&As[0][0]);
    ab[1] = (uint32_t)__cvta_generic_to_shared(&As[1][0]);
    bb[0] = (uint32_t)__cvta_generic_to_shared(&Bs[0][0]);
    bb[1] = (uint32_t)__cvta_generic_to_shared(&Bs[1][0]);

    uint32_t aoff[2], boff[2];
    const float* agp[2];
    const float* bgp[2];
    #pragma unroll
    for (int i = 0; i < 2; i++) {
        int slot = tid + (i << 8);
        int m = slot >> 2, seg = slot & 3;
        int gr = rowTile + m; if (gr >= M) gr = M - 1;
        aoff[i] = (uint32_t)(m * AST + seg * 4) * 4;
        agp[i]  = A + (size_t)gr * K + seg * 4;
        int k = slot >> 5, sg = slot & 31;
        boff[i] = (uint32_t)(k * BST + sg * 4) * 4;
        bgp[i]  = W + (size_t)k * 256 + colTile + sg * 4;
    }

    auto stage = [&](int k0, int buf) {
        #pragma unroll
        for (int i = 0; i < 2; i++)
            cp16(ab[buf] + aoff[i], agp[i] + k0);
        #pragma unroll
        for (int i = 0; i < 2; i++)
            cp16(bb[buf] + boff[i], bgp[i] + (size_t)k0 * 256);
    };

    stage(0, 0);
    cp_commit();

    for (int s = 0; s < S; s++) {
        const int buf = s & 1;
        if (s + 1 < S) {
            stage((s + 1) << 4, buf ^ 1);
            cp_commit();
            asm volatile("cp.async.wait_group 1;");
        } else {
            asm volatile("cp.async.wait_group 0;");
        }
        __syncthreads();

        const float* as = As[buf];
        const float* bs = Bs[buf];

        uint32_t ah[2][4], al[2][4];
        #pragma unroll
        for (int mt = 0; mt < 2; mt++) {
            const int m0 = wm * 32 + mt * 16 + g;
            const int m1 = m0 + 8;
            splitv(*(const float2*)&as[m0 * AST + 2 * tig],     ah[mt][0], al[mt][0]);
            splitv(*(const float2*)&as[m1 * AST + 2 * tig],     ah[mt][1], al[mt][1]);
            splitv(*(const float2*)&as[m0 * AST + 2 * tig + 8], ah[mt][2], al[mt][2]);
            splitv(*(const float2*)&as[m1 * AST + 2 * tig + 8], ah[mt][3], al[mt][3]);
        }

        #pragma unroll
        for (int half = 0; half < 2; half++) {
            uint32_t bh[4][2], bl[4][2];
            #pragma unroll
            for (int q = 0; q < 4; q++) {
                const int n = wn * 64 + (half * 4 + q) * 8 + g;
                float2 v0, v1;
                v0.x = bs[(2 * tig)     * BST + n];
                v0.y = bs[(2 * tig + 1) * BST + n];
                v1.x = bs[(2 * tig + 8) * BST + n];
                v1.y = bs[(2 * tig + 9) * BST + n];
                splitv(v0, bh[q][0], bl[q][0]);
                splitv(v1, bh[q][1], bl[q][1]);
            }
            #pragma unroll
            for (int mt = 0; mt < 2; mt++)
                #pragma unroll
                for (int q = 0; q < 4; q++) {
                    const int nt = half * 4 + q;
                    mma16(acc[mt][nt], ah[mt], bh[q]);
                    mma16(acc[mt][nt], ah[mt], bl[q]);
                    mma16(acc[mt][nt], al[mt], bh[q]);
                }
        }
        if (s + 1 < S) __syncthreads();
    }

    #pragma unroll
    for (int mt = 0; mt < 2; mt++) {
        const int r0 = rowTile + wm * 32 + mt * 16 + g;
        const int r1 = r0 + 8;
        #pragma unroll
        for (int nt = 0; nt < 8; nt++) {
            const int col = colTile + wn * 64 + nt * 8 + tig * 2;
            float2 bv = *(const float2*)(bias + col);
            if (r0 < M) {
                float2 v;
                v.x = acc[mt][nt][0] + bv.x;
                v.y = acc[mt][nt][1] + bv.y;
                if (RELU) { v.x = fmaxf(v.x, 0.f); v.y = fmaxf(v.y, 0.f); }
                *(float2*)(C + (size_t)r0 * 256 + col) = v;
                if (DUAL) *(float2*)(C2 + (size_t)r0 * 256 + col) = v;
            }
            if (r1 < M) {
                float2 v;
                v.x = acc[mt][nt][2] + bv.x;
                v.y = acc[mt][nt][3] + bv.y;
                if (RELU) { v.x = fmaxf(v.x, 0.f); v.y = fmaxf(v.y, 0.f); }
                *(float2*)(C + (size_t)r1 * 256 + col) = v;
                if (DUAL) *(float2*)(C2 + (size_t)r1 * 256 + col) = v;
            }
        }
    }
}

// ---------------------------------------------------------------------------
// Edge-fused GEMM on dst-sorted edges (R14 design + hoisted staging).
// ---------------------------------------------------------------------------
__global__ __launch_bounds__(256, 2)
void edge_gemm(const float* __restrict__ A, const float* __restrict__ W,
               const float* __restrict__ bias,
               const int* __restrict__ ei, const int* __restrict__ perm,
               const float* __restrict__ hg, float* __restrict__ agg)
{
    extern __shared__ float esm[];
    float* Asm[2] = { esm + EOFF_A0, esm + EOFF_A1 };
    float* Bsm[2] = { esm + EOFF_B0, esm + EOFF_B1 };
    float* Hs     = esm + EOFF_H;
    __shared__ int pidx[128];
    __shared__ int src_s[128];
    __shared__ int dst_s[128];

    const int tid  = threadIdx.x;
    const int lane = tid & 31;
    const int wid  = tid >> 5;
    const int g    = lane >> 2;
    const int tig  = lane & 3;
    const int wm   = wid & 3;
    const int wn   = wid >> 2;
    const int rowTile = blockIdx.y * 128;
    const int colTile = blockIdx.x * 128;

    if (tid < 128) {
        int pe = perm[rowTile + tid];
        pidx[tid] = pe;
        src_s[tid] = ei[pe];
        dst_s[tid] = ei[NE + pe];
    }
    __syncthreads();

    float acc[2][8][4];
    #pragma unroll
    for (int mt = 0; mt < 2; mt++)
        #pragma unroll
        for (int nt = 0; nt < 8; nt++)
            #pragma unroll
            for (int j = 0; j < 4; j++) acc[mt][nt][j] = 0.f;

    uint32_t ab[2], bb[2], hbase;
    ab[0] = (uint32_t)__cvta_generic_to_shared(Asm[0]);
    ab[1] = (uint32_t)__cvta_generic_to_shared(Asm[1]);
    bb[0] = (uint32_t)__cvta_generic_to_shared(Bsm[0]);
    bb[1] = (uint32_t)__cvta_generic_to_shared(Bsm[1]);
    hbase = (uint32_t)__cvta_generic_to_shared(Hs);

    uint32_t aoff[2], boff[2];
    const float* agp[2];
    const float* bgp[2];
    #pragma unroll
    for (int i = 0; i < 2; i++) {
        int slot = tid + (i << 8);
        int m = slot >> 2, seg = slot & 3;
        int el = (m & ~31) + 4 * (m & 7) + ((m >> 3) & 3);
        int pe = pidx[el];
        aoff[i] = (uint32_t)(m * AST + seg * 4) * 4;
        agp[i]  = A + (size_t)pe * 64 + seg * 4;
        int k = slot >> 5, sg = slot & 31;
        boff[i] = (uint32_t)(k * BST + sg * 4) * 4;
        bgp[i]  = W + (size_t)k * 256 + colTile + sg * 4;
    }

    auto stage = [&](int k0, int buf) {
        #pragma unroll
        for (int i = 0; i < 2; i++)
            cp16(ab[buf] + aoff[i], agp[i] + k0);
        #pragma unroll
        for (int i = 0; i < 2; i++)
            cp16(bb[buf] + boff[i], bgp[i] + (size_t)k0 * 256);
    };

    stage(0, 0);
    cp_commit();

    #pragma unroll
    for (int i = 0; i < 16; i++) {
        int c2 = tid + (i << 8);
        int p = c2 >> 5, cseg = c2 & 31;
        int el = (p & ~31) + 4 * (p & 7) + ((p >> 3) & 3);
        int src = src_s[el];
        cp16(hbase + (uint32_t)(p * HST + cseg * 4) * 4,
             hg + (size_t)src * 256 + colTile + cseg * 4);
    }
    cp_commit();

    #pragma unroll
    for (int s = 0; s < 4; s++) {
        const int buf = s & 1;
        if (s + 1 < 4) {
            stage((s + 1) << 4, buf ^ 1);
            cp_commit();
        }
        if (s == 0)      asm volatile("cp.async.wait_group 2;");
        else if (s < 3)  asm volatile("cp.async.wait_group 1;");
        else             asm volatile("cp.async.wait_group 0;");
        __syncthreads();

        const float* as = Asm[buf];
        const float* bs = Bsm[buf];

        uint32_t ah[2][4], al[2][4];
        #pragma unroll
        for (int mt = 0; mt < 2; mt++) {
            const int m0 = wm * 32 + mt * 16 + g;
            const int m1 = m0 + 8;
            splitv(*(const float2*)&as[m0 * AST + 2 * tig],     ah[mt][0], al[mt][0]);
            splitv(*(const float2*)&as[m1 * AST + 2 * tig],     ah[mt][1], al[mt][1]);
            splitv(*(const float2*)&as[m0 * AST + 2 * tig + 8], ah[mt][2], al[mt][2]);
            splitv(*(const float2*)&as[m1 * AST + 2 * tig + 8], ah[mt][3], al[mt][3]);
        }

        #pragma unroll
        for (int half = 0; half < 2; half++) {
            uint32_t bh[4][2], bl[4][2];
            #pragma unroll
            for (int q = 0; q < 4; q++) {
                const int n = wn * 64 + (half * 4 + q) * 8 + g;
                float2 v0, v1;
                v0.x = bs[(2 * tig)     * BST + n];
                v0.y = bs[(2 * tig + 1) * BST + n];
                v1.x = bs[(2 * tig + 8) * BST + n];
                v1.y = bs[(2 * tig + 9) * BST + n];
                splitv(v0, bh[q][0], bl[q][0]);
                splitv(v1, bh[q][1], bl[q][1]);
            }
            #pragma unroll
            for (int mt = 0; mt < 2; mt++)
                #pragma unroll
                for (int q = 0; q < 4; q++) {
                    const int nt = half * 4 + q;
                    mma16(acc[mt][nt], ah[mt], bh[q]);
                    mma16(acc[mt][nt], ah[mt], bl[q]);
                    mma16(acc[mt][nt], al[mt], bh[q]);
                }
        }
        if (s + 1 < 4) __syncthreads();
    }

    const int eb = wm * 32 + 4 * g;
    const int d0 = dst_s[eb + 0], d1 = dst_s[eb + 1];
    const int d2 = dst_s[eb + 2], d3 = dst_s[eb + 3];
    const int hrow = wm * 32 + g;
    const bool even = (tig & 1) == 0;

    #pragma unroll
    for (int nt = 0; nt < 8; nt++) {
        float p[2][4];
        #pragma unroll
        for (int mt = 0; mt < 2; mt++)
            #pragma unroll
            for (int j = 0; j < 4; j++)
                p[mt][j] = __shfl_xor_sync(0xffffffffu, acc[mt][nt][j], 1);

        if (even) {
            const int lcol = wn * 64 + nt * 8 + tig * 2;
            const int col = colTile + lcol;
            float4 bv = *(const float4*)(bias + col);
            float4 v0, v1, v2, v3;
            v0.x = acc[0][nt][0] + bv.x; v0.y = acc[0][nt][1] + bv.y;
            v0.z = p[0][0] + bv.z;       v0.w = p[0][1] + bv.w;
            v1.x = acc[0][nt][2] + bv.x; v1.y = acc[0][nt][3] + bv.y;
            v1.z = p[0][2] + bv.z;       v1.w = p[0][3] + bv.w;
            v2.x = acc[1][nt][0] + bv.x; v2.y = acc[1][nt][1] + bv.y;
            v2.z = p[1][0] + bv.z;       v2.w = p[1][1] + bv.w;
            v3.x = acc[1][nt][2] + bv.x; v3.y = acc[1][nt][3] + bv.y;
            v3.z = p[1][2] + bv.z;       v3.w = p[1][3] + bv.w;

            float4 h0 = *(const float4*)(Hs + (hrow +  0) * HST + lcol);
            float4 h1 = *(const float4*)(Hs + (hrow +  8) * HST + lcol);
            float4 h2 = *(const float4*)(Hs + (hrow + 16) * HST + lcol);
            float4 h3 = *(const float4*)(Hs + (hrow + 24) * HST + lcol);

            v0.x = fmaxf(v0.x + h0.x, 0.f); v0.y = fmaxf(v0.y + h0.y, 0.f);
            v0.z = fmaxf(v0.z + h0.z, 0.f); v0.w = fmaxf(v0.w + h0.w, 0.f);
            v1.x = fmaxf(v1.x + h1.x, 0.f); v1.y = fmaxf(v1.y + h1.y, 0.f);
            v1.z = fmaxf(v1.z + h1.z, 0.f); v1.w = fmaxf(v1.w + h1.w, 0.f);
            v2.x = fmaxf(v2.x + h2.x, 0.f); v2.y = fmaxf(v2.y + h2.y, 0.f);
            v2.z = fmaxf(v2.z + h2.z, 0.f); v2.w = fmaxf(v2.w + h2.w, 0.f);
            v3.x = fmaxf(v3.x + h3.x, 0.f); v3.y = fmaxf(v3.y + h3.y, 0.f);
            v3.z = fmaxf(v3.z + h3.z, 0.f); v3.w = fmaxf(v3.w + h3.w, 0.f);

            float4 cur = v0; int cd = d0;
            if (d1 == cd) {
                cur.x += v1.x; cur.y += v1.y; cur.z += v1.z; cur.w += v1.w;
            } else {
                red_add_v4(agg + (size_t)cd * 256 + col, cur);
                cur = v1; cd = d1;
            }
            if (d2 == cd) {
                cur.x += v2.x; cur.y += v2.y; cur.z += v2.z; cur.w += v2.w;
            } else {
                red_add_v4(agg + (size_t)cd * 256 + col, cur);
                cur = v2; cd = d2;
            }
            if (d3 == cd) {
                cur.x += v3.x; cur.y += v3.y; cur.z += v3.z; cur.w += v3.w;
            } else {
                red_add_v4(agg + (size_t)cd * 256 + col, cur);
                cur = v3; cd = d3;
            }
            red_add_v4(agg + (size_t)cd * 256 + col, cur);
        }
    }
}

// One block (64 threads) per node: scatter mean-pool contributions.
__global__ void pool_kernel(const float* __restrict__ h,
                            const int* __restrict__ batch,
                            float* __restrict__ pool, float* __restrict__ cnt)
{
    const int node = blockIdx.x;
    const int gph = batch[node];
    const int t = threadIdx.x;
    float4 v = *reinterpret_cast<const float4*>(h + (size_t)node * 256 + t * 4);
    red_add_v4(pool + (size_t)gph * 256 + t * 4, v);
    if (t == 0) atomicAdd(cnt + gph, 1.0f);
}

// One block per graph: mean -> relu(g@W1+b1)@W2+b2 -> L2 normalize.
__global__ void final_kernel(const float* __restrict__ pool,
                             const float* __restrict__ cnt,
                             const float* __restrict__ W1, const float* __restrict__ b1,
                             const float* __restrict__ W2, const float* __restrict__ b2,
                             float* __restrict__ out)
{
    const int gph = blockIdx.x;
    const int j = threadIdx.x;
    __shared__ float s[256];
    __shared__ float s2[256];
    __shared__ float redbuf[8];
    __shared__ float snorm;

    const float inv = 1.0f / fmaxf(cnt[gph], 1.0f);
    s[j] = pool[gph * 256 + j] * inv;
    __syncthreads();

    float t = b1[j];
    #pragma unroll 8
    for (int k = 0; k < 256; k++) t = fmaf(s[k], W1[k * 256 + j], t);
    t = fmaxf(t, 0.f);
    s2[j] = t;
    __syncthreads();

    float o = b2[j];
    #pragma unroll 8
    for (int k = 0; k < 256; k++) o = fmaf(s2[k], W2[k * 256 + j], o);

    float sq = o * o;
    #pragma unroll
    for (int off = 16; off > 0; off >>= 1)
        sq += __shfl_down_sync(0xffffffffu, sq, off);
    if ((j & 31) == 0) redbuf[j >> 5] = sq;
    __syncthreads();
    if (j == 0) {
        float ss = 0.f;
        #pragma unroll
        for (int w = 0; w < 8; w++) ss += redbuf[w];
        snorm = fmaxf(sqrtf(ss), 1e-12f);
    }
    __syncthreads();

    out[gph * 256 + j] = o / snorm;
}

extern "C" void kernel_launch(void* const* d_in, const int* in_sizes, int n_in,
                              void* d_out, int out_size)
{
    const float* x   = (const float*)d_in[0];
    const int*   ei  = (const int*)  d_in[1];
    const float* ea  = (const float*)d_in[2];
    const int*   bi  = (const int*)  d_in[3];
    const float* xW  = (const float*)d_in[4];
    const float* xb  = (const float*)d_in[5];
    const float* eW  = (const float*)d_in[6];
    const float* eb  = (const float*)d_in[7];
    const float* W1  = (const float*)d_in[8];
    const float* b1  = (const float*)d_in[9];
    const float* W2  = (const float*)d_in[10];
    const float* b2  = (const float*)d_in[11];
    const float* oW1 = (const float*)d_in[12];
    const float* ob1 = (const float*)d_in[13];
    const float* oW2 = (const float*)d_in[14];
    const float* ob2 = (const float*)d_in[15];
    float* out = (float*)d_out;

    float *ph, *pagg, *pt, *ppool, *pcnt;
    int *phisto, *pperm;
    cudaGetSymbolAddress((void**)&ph,    g_h);
    cudaGetSymbolAddress((void**)&pagg,  g_agg);
    cudaGetSymbolAddress((void**)&pt,    g_t);
    cudaGetSymbolAddress((void**)&ppool, g_pool);
    cudaGetSymbolAddress((void**)&pcnt,  g_cnt);
    cudaGetSymbolAddress((void**)&phisto, g_histo);
    cudaGetSymbolAddress((void**)&pperm,  g_perm);

    cudaFuncSetAttribute(edge_gemm,
                         cudaFuncAttributeMaxDynamicSharedMemorySize, ESMEM_BYTES);

    dim3 gNode(2, (NN + 127) / 128);   // (2, 157)
    dim3 gEdge(2, NE / 128);           // (2, 2500)

    // ---- counting sort of edges by dst ----
    zero4<<<(NN / 4 + 255) / 256, 256>>>((float4*)phisto, NN / 4);
    hist_kernel<<<(NE + 255) / 256, 256>>>(ei, phisto);
    scan_kernel<<<1, 1024>>>(phisto);
    scatter_kernel<<<(NE + 255) / 256, 256>>>(ei, phisto, pperm);

    // h = x @ xproj_W + xproj_b; agg = h (dual store)
    mma_gemm<false, true><<<gNode, 256>>>(x, xW, xb, ph, pagg, NN, 128);

    for (int l = 0; l < 3; l++) {
        edge_gemm<<<gEdge, 256, ESMEM_BYTES>>>(
            ea, eW + l * 64 * 256, eb + l * 256, ei, pperm, ph, pagg);
        mma_gemm<true, false><<<gNode, 256>>>(
            pagg, W1 + l * 256 * 256, b1 + l * 256, pt, nullptr, NN, 256);
        if (l < 2)
            mma_gemm<true, true><<<gNode, 256>>>(
                pt, W2 + l * 256 * 256, b2 + l * 256, ph, pagg, NN, 256);
        else
            mma_gemm<true, false><<<gNode, 256>>>(
                pt, W2 + l * 256 * 256, b2 + l * 256, ph, nullptr, NN, 256);
    }

    // mean pool
    zero4<<<(NG * 64 + 255) / 256, 256>>>((float4*)ppool, NG * 64);
    zero4<<<1, 256>>>((float4*)pcnt, NG / 4);
    pool_kernel<<<NN, 64>>>(ph, bi, ppool, pcnt);

    // graph head + normalize
    final_kernel<<<NG, 256>>>(ppool, pcnt, oW1, ob1, oW2, ob2, out);
}

// round 17
// speedup vs baseline: 1.2572x; 1.0058x over previous
#include <cuda_runtime.h>
#include <math.h>
#include <stdint.h>

#define NN 20000
#define NE 320000
#define NG 64

// ---- scratch (device globals; no allocation allowed) ----
__device__ __align__(16) float g_h  [NN * 256];
__device__ __align__(16) float g_agg[NN * 256];
__device__ __align__(16) float g_t  [NN * 256];
__device__ __align__(16) float g_pool[NG * 256];
__device__ float g_cnt[NG];
__device__ __align__(16) int g_histo[NN];
__device__ __align__(16) int g_perm[NE];

// ---------------- PTX helpers ----------------
__device__ __forceinline__ void splitv(float2 v, uint32_t& h, uint32_t& l) {
    asm("cvt.rn.bf16x2.f32 %0, %1, %2;" : "=r"(h) : "f"(v.y), "f"(v.x));
    float f0 = __uint_as_float(h << 16);
    float f1 = __uint_as_float(h & 0xFFFF0000u);
    asm("cvt.rn.bf16x2.f32 %0, %1, %2;" : "=r"(l) : "f"(v.y - f1), "f"(v.x - f0));
}

__device__ __forceinline__ void mma16(float* d, const uint32_t* a, const uint32_t* b) {
    asm volatile(
        "mma.sync.aligned.m16n8k16.row.col.f32.bf16.bf16.f32 "
        "{%0,%1,%2,%3}, {%4,%5,%6,%7}, {%8,%9}, {%0,%1,%2,%3};"
        : "+f"(d[0]), "+f"(d[1]), "+f"(d[2]), "+f"(d[3])
        : "r"(a[0]), "r"(a[1]), "r"(a[2]), "r"(a[3]), "r"(b[0]), "r"(b[1]));
}

__device__ __forceinline__ void cp16(uint32_t saddr, const void* gptr) {
    asm volatile("cp.async.cg.shared.global [%0], [%1], 16;" :: "r"(saddr), "l"(gptr));
}
__device__ __forceinline__ void cp_commit() { asm volatile("cp.async.commit_group;"); }

__device__ __forceinline__ void red_add_v4(float* addr, float4 v) {
    asm volatile("red.global.add.v4.f32 [%0], {%1,%2,%3,%4};"
                 :: "l"(addr), "f"(v.x), "f"(v.y), "f"(v.z), "f"(v.w) : "memory");
}

// ---------------- counting sort of edges by dst ----------------
__global__ void hist_kernel(const int* __restrict__ ei, int* __restrict__ histo) {
    int e = blockIdx.x * blockDim.x + threadIdx.x;
    if (e < NE) atomicAdd(&histo[ei[NE + e]], 1);
}

__global__ void scan_kernel(int* __restrict__ histo) {
    __shared__ int s[1024];
    const int t = threadIdx.x;
    const int CH = (NN + 1023) / 1024;   // 20
    const int base = t * CH;
    int sum = 0;
    #pragma unroll
    for (int i = 0; i < CH; i++) {
        int idx = base + i;
        if (idx < NN) sum += histo[idx];
    }
    s[t] = sum;
    __syncthreads();
    for (int d = 1; d < 1024; d <<= 1) {
        int add = (t >= d) ? s[t - d] : 0;
        __syncthreads();
        s[t] += add;
        __syncthreads();
    }
    int run = s[t] - sum;
    #pragma unroll
    for (int i = 0; i < CH; i++) {
        int idx = base + i;
        if (idx < NN) {
            int c = histo[idx];
            histo[idx] = run;
            run += c;
        }
    }
}

__global__ void scatter_kernel(const int* __restrict__ ei,
                               int* __restrict__ histo, int* __restrict__ perm) {
    int e = blockIdx.x * blockDim.x + threadIdx.x;
    if (e < NE) {
        int pos = atomicAdd(&histo[ei[NE + e]], 1);
        perm[pos] = e;
    }
}

// ---- smem strides (floats) ----
#define AST 20     // A: [rows][16 k] stride 20
#define BST 140    // B: [16 k][128 n] stride 140
#define HST 136    // H: [128 rows][128 cols] stride 136

// node GEMM: 3-stage dynamic smem
#define NA_SZ (128 * AST)
#define NB_SZ (16 * BST)
#define NSMEM_FLOATS (3 * NA_SZ + 3 * NB_SZ)
#define NSMEM_BYTES  (NSMEM_FLOATS * 4)     // 57600

// edge kernel dynamic smem (2-stage + H), unchanged from R14
#define EOFF_A0 0
#define EOFF_A1 (128 * AST)
#define EOFF_B0 (2 * 128 * AST)
#define EOFF_B1 (2 * 128 * AST + 16 * BST)
#define EOFF_H  (2 * 128 * AST + 2 * 16 * BST)
#define ESMEM_FLOATS (EOFF_H + 128 * HST)
#define ESMEM_BYTES  (ESMEM_FLOATS * 4)     // 108032

// ---------------------------------------------------------------------------
// Node GEMM: CTA tile 128x128, warp tile 32x64, split-BF16 (3x m16n8k16),
// 3-stage pipeline, ONE barrier per stage, 2-deep prefetch.
// DUAL: also store into C2.
// ---------------------------------------------------------------------------
template<bool RELU, bool DUAL>
__global__ __launch_bounds__(256, 2)
void mma_gemm(const float* __restrict__ A, const float* __restrict__ W,
              const float* __restrict__ bias, float* __restrict__ C,
              float* __restrict__ C2, int M, int K)
{
    extern __shared__ float nsm[];
    float* Abase = nsm;                 // 3 x NA_SZ
    float* Bbase = nsm + 3 * NA_SZ;     // 3 x NB_SZ

    const int tid  = threadIdx.x;
    const int lane = tid & 31;
    const int wid  = tid >> 5;
    const int g    = lane >> 2;
    const int tig  = lane & 3;
    const int wm   = wid & 3;
    const int wn   = wid >> 2;
    const int rowTile = blockIdx.y * 128;
    const int colTile = blockIdx.x * 128;

    float acc[2][8][4];
    #pragma unroll
    for (int mt = 0; mt < 2; mt++)
        #pragma unroll
        for (int nt = 0; nt < 8; nt++)
            #pragma unroll
            for (int j = 0; j < 4; j++) acc[mt][nt][j] = 0.f;

    const int S = K >> 4;

    const uint32_t abs0 = (uint32_t)__cvta_generic_to_shared(Abase);
    const uint32_t bbs0 = (uint32_t)__cvta_generic_to_shared(Bbase);

    // hoisted staging addresses (loop-invariant except k0/buf)
    uint32_t aoff[2], boff[2];
    const float* agp[2];
    const float* bgp[2];
    #pragma unroll
    for (int i = 0; i < 2; i++) {
        int slot = tid + (i << 8);
        int m = slot >> 2, seg = slot & 3;
        int gr = rowTile + m; if (gr >= M) gr = M - 1;
        aoff[i] = (uint32_t)(m * AST + seg * 4) * 4;
        agp[i]  = A + (size_t)gr * K + seg * 4;
        int k = slot >> 5, sg = slot & 31;
        boff[i] = (uint32_t)(k * BST + sg * 4) * 4;
        bgp[i]  = W + (size_t)k * 256 + colTile + sg * 4;
    }

    auto stage = [&](int k0, int buf) {
        const uint32_t ab = abs0 + (uint32_t)(buf * NA_SZ) * 4;
        const uint32_t bb = bbs0 + (uint32_t)(buf * NB_SZ) * 4;
        #pragma unroll
        for (int i = 0; i < 2; i++)
            cp16(ab + aoff[i], agp[i] + k0);
        #pragma unroll
        for (int i = 0; i < 2; i++)
            cp16(bb + boff[i], bgp[i] + (size_t)k0 * 256);
    };

    stage(0, 0);
    cp_commit();
    if (S > 1) { stage(16, 1); cp_commit(); }

    int cb = 0;   // compute buffer index for stage s
    for (int s = 0; s < S; s++) {
        if (s + 1 < S) asm volatile("cp.async.wait_group 1;");
        else           asm volatile("cp.async.wait_group 0;");
        __syncthreads();   // publish stage s; all warps past compute of s-1

        if (s + 2 < S) {
            int pb = cb + 2; if (pb >= 3) pb -= 3;   // == (s-1)%3, freed by barrier
            stage((s + 2) << 4, pb);
            cp_commit();
        }

        const float* as = Abase + cb * NA_SZ;
        const float* bs = Bbase + cb * NB_SZ;

        uint32_t ah[2][4], al[2][4];
        #pragma unroll
        for (int mt = 0; mt < 2; mt++) {
            const int m0 = wm * 32 + mt * 16 + g;
            const int m1 = m0 + 8;
            splitv(*(const float2*)&as[m0 * AST + 2 * tig],     ah[mt][0], al[mt][0]);
            splitv(*(const float2*)&as[m1 * AST + 2 * tig],     ah[mt][1], al[mt][1]);
            splitv(*(const float2*)&as[m0 * AST + 2 * tig + 8], ah[mt][2], al[mt][2]);
            splitv(*(const float2*)&as[m1 * AST + 2 * tig + 8], ah[mt][3], al[mt][3]);
        }

        #pragma unroll
        for (int half = 0; half < 2; half++) {
            uint32_t bh[4][2], bl[4][2];
            #pragma unroll
            for (int q = 0; q < 4; q++) {
                const int n = wn * 64 + (half * 4 + q) * 8 + g;
                float2 v0, v1;
                v0.x = bs[(2 * tig)     * BST + n];
                v0.y = bs[(2 * tig + 1) * BST + n];
                v1.x = bs[(2 * tig + 8) * BST + n];
                v1.y = bs[(2 * tig + 9) * BST + n];
                splitv(v0, bh[q][0], bl[q][0]);
                splitv(v1, bh[q][1], bl[q][1]);
            }
            #pragma unroll
            for (int mt = 0; mt < 2; mt++)
                #pragma unroll
                for (int q = 0; q < 4; q++) {
                    const int nt = half * 4 + q;
                    mma16(acc[mt][nt], ah[mt], bh[q]);
                    mma16(acc[mt][nt], ah[mt], bl[q]);
                    mma16(acc[mt][nt], al[mt], bh[q]);
                }
        }
        cb = (cb + 1 == 3) ? 0 : cb + 1;
    }

    #pragma unroll
    for (int mt = 0; mt < 2; mt++) {
        const int r0 = rowTile + wm * 32 + mt * 16 + g;
        const int r1 = r0 + 8;
        #pragma unroll
        for (int nt = 0; nt < 8; nt++) {
            const int col = colTile + wn * 64 + nt * 8 + tig * 2;
            float2 bv = *(const float2*)(bias + col);
            if (r0 < M) {
                float2 v;
                v.x = acc[mt][nt][0] + bv.x;
                v.y = acc[mt][nt][1] + bv.y;
                if (RELU) { v.x = fmaxf(v.x, 0.f); v.y = fmaxf(v.y, 0.f); }
                *(float2*)(C + (size_t)r0 * 256 + col) = v;
                if (DUAL) *(float2*)(C2 + (size_t)r0 * 256 + col) = v;
            }
            if (r1 < M) {
                float2 v;
                v.x = acc[mt][nt][2] + bv.x;
                v.y = acc[mt][nt][3] + bv.y;
                if (RELU) { v.x = fmaxf(v.x, 0.f); v.y = fmaxf(v.y, 0.f); }
                *(float2*)(C + (size_t)r1 * 256 + col) = v;
                if (DUAL) *(float2*)(C2 + (size_t)r1 * 256 + col) = v;
            }
        }
    }
}

// ---------------------------------------------------------------------------
// Edge-fused GEMM on dst-sorted edges (R14/R16 design, unchanged).
// ---------------------------------------------------------------------------
__global__ __launch_bounds__(256, 2)
void edge_gemm(const float* __restrict__ A, const float* __restrict__ W,
               const float* __restrict__ bias,
               const int* __restrict__ ei, const int* __restrict__ perm,
               const float* __restrict__ hg, float* __restrict__ agg)
{
    extern __shared__ float esm[];
    float* Asm[2] = { esm + EOFF_A0, esm + EOFF_A1 };
    float* Bsm[2] = { esm + EOFF_B0, esm + EOFF_B1 };
    float* Hs     = esm + EOFF_H;
    __shared__ int pidx[128];
    __shared__ int src_s[128];
    __shared__ int dst_s[128];

    const int tid  = threadIdx.x;
    const int lane = tid & 31;
    const int wid  = tid >> 5;
    const int g    = lane >> 2;
    const int tig  = lane & 3;
    const int wm   = wid & 3;
    const int wn   = wid >> 2;
    const int rowTile = blockIdx.y * 128;
    const int colTile = blockIdx.x * 128;

    if (tid < 128) {
        int pe = perm[rowTile + tid];
        pidx[tid] = pe;
        src_s[tid] = ei[pe];
        dst_s[tid] = ei[NE + pe];
    }
    __syncthreads();

    float acc[2][8][4];
    #pragma unroll
    for (int mt = 0; mt < 2; mt++)
        #pragma unroll
        for (int nt = 0; nt < 8; nt++)
            #pragma unroll
            for (int j = 0; j < 4; j++) acc[mt][nt][j] = 0.f;

    uint32_t ab[2], bb[2], hbase;
    ab[0] = (uint32_t)__cvta_generic_to_shared(Asm[0]);
    ab[1] = (uint32_t)__cvta_generic_to_shared(Asm[1]);
    bb[0] = (uint32_t)__cvta_generic_to_shared(Bsm[0]);
    bb[1] = (uint32_t)__cvta_generic_to_shared(Bsm[1]);
    hbase = (uint32_t)__cvta_generic_to_shared(Hs);

    uint32_t aoff[2], boff[2];
    const float* agp[2];
    const float* bgp[2];
    #pragma unroll
    for (int i = 0; i < 2; i++) {
        int slot = tid + (i << 8);
        int m = slot >> 2, seg = slot & 3;
        int el = (m & ~31) + 4 * (m & 7) + ((m >> 3) & 3);
        int pe = pidx[el];
        aoff[i] = (uint32_t)(m * AST + seg * 4) * 4;
        agp[i]  = A + (size_t)pe * 64 + seg * 4;
        int k = slot >> 5, sg = slot & 31;
        boff[i] = (uint32_t)(k * BST + sg * 4) * 4;
        bgp[i]  = W + (size_t)k * 256 + colTile + sg * 4;
    }

    auto stage = [&](int k0, int buf) {
        #pragma unroll
        for (int i = 0; i < 2; i++)
            cp16(ab[buf] + aoff[i], agp[i] + k0);
        #pragma unroll
        for (int i = 0; i < 2; i++)
            cp16(bb[buf] + boff[i], bgp[i] + (size_t)k0 * 256);
    };

    stage(0, 0);
    cp_commit();

    #pragma unroll
    for (int i = 0; i < 16; i++) {
        int c2 = tid + (i << 8);
        int p = c2 >> 5, cseg = c2 & 31;
        int el = (p & ~31) + 4 * (p & 7) + ((p >> 3) & 3);
        int src = src_s[el];
        cp16(hbase + (uint32_t)(p * HST + cseg * 4) * 4,
             hg + (size_t)src * 256 + colTile + cseg * 4);
    }
    cp_commit();

    #pragma unroll
    for (int s = 0; s < 4; s++) {
        const int buf = s & 1;
        if (s + 1 < 4) {
            stage((s + 1) << 4, buf ^ 1);
            cp_commit();
        }
        if (s == 0)      asm volatile("cp.async.wait_group 2;");
        else if (s < 3)  asm volatile("cp.async.wait_group 1;");
        else             asm volatile("cp.async.wait_group 0;");
        __syncthreads();

        const float* as = Asm[buf];
        const float* bs = Bsm[buf];

        uint32_t ah[2][4], al[2][4];
        #pragma unroll
        for (int mt = 0; mt < 2; mt++) {
            const int m0 = wm * 32 + mt * 16 + g;
            const int m1 = m0 + 8;
            splitv(*(const float2*)&as[m0 * AST + 2 * tig],     ah[mt][0], al[mt][0]);
            splitv(*(const float2*)&as[m1 * AST + 2 * tig],     ah[mt][1], al[mt][1]);
            splitv(*(const float2*)&as[m0 * AST + 2 * tig + 8], ah[mt][2], al[mt][2]);
            splitv(*(const float2*)&as[m1 * AST + 2 * tig + 8], ah[mt][3], al[mt][3]);
        }

        #pragma unroll
        for (int half = 0; half < 2; half++) {
            uint32_t bh[4][2], bl[4][2];
            #pragma unroll
            for (int q = 0; q < 4; q++) {
                const int n = wn * 64 + (half * 4 + q) * 8 + g;
                float2 v0, v1;
                v0.x = bs[(2 * tig)     * BST + n];
                v0.y = bs[(2 * tig + 1) * BST + n];
                v1.x = bs[(2 * tig + 8) * BST + n];
                v1.y = bs[(2 * tig + 9) * BST + n];
                splitv(v0, bh[q][0], bl[q][0]);
                splitv(v1, bh[q][1], bl[q][1]);
            }
            #pragma unroll
            for (int mt = 0; mt < 2; mt++)
                #pragma unroll
                for (int q = 0; q < 4; q++) {
                    const int nt = half * 4 + q;
                    mma16(acc[mt][nt], ah[mt], bh[q]);
                    mma16(acc[mt][nt], ah[mt], bl[q]);
                    mma16(acc[mt][nt], al[mt], bh[q]);
                }
        }
        if (s + 1 < 4) __syncthreads();
    }

    const int eb = wm * 32 + 4 * g;
    const int d0 = dst_s[eb + 0], d1 = dst_s[eb + 1];
    const int d2 = dst_s[eb + 2], d3 = dst_s[eb + 3];
    const int hrow = wm * 32 + g;
    const bool even = (tig & 1) == 0;

    #pragma unroll
    for (int nt = 0; nt < 8; nt++) {
        float p[2][4];
        #pragma unroll
        for (int mt = 0; mt < 2; mt++)
            #pragma unroll
            for (int j = 0; j < 4; j++)
                p[mt][j] = __shfl_xor_sync(0xffffffffu, acc[mt][nt][j], 1);

        if (even) {
            const int lcol = wn * 64 + nt * 8 + tig * 2;
            const int col = colTile + lcol;
            float4 bv = *(const float4*)(bias + col);
            float4 v0, v1, v2, v3;
            v0.x = acc[0][nt][0] + bv.x; v0.y = acc[0][nt][1] + bv.y;
            v0.z = p[0][0] + bv.z;       v0.w = p[0][1] + bv.w;
            v1.x = acc[0][nt][2] + bv.x; v1.y = acc[0][nt][3] + bv.y;
            v1.z = p[0][2] + bv.z;       v1.w = p[0][3] + bv.w;
            v2.x = acc[1][nt][0] + bv.x; v2.y = acc[1][nt][1] + bv.y;
            v2.z = p[1][0] + bv.z;       v2.w = p[1][1] + bv.w;
            v3.x = acc[1][nt][2] + bv.x; v3.y = acc[1][nt][3] + bv.y;
            v3.z = p[1][2] + bv.z;       v3.w = p[1][3] + bv.w;

            float4 h0 = *(const float4*)(Hs + (hrow +  0) * HST + lcol);
            float4 h1 = *(const float4*)(Hs + (hrow +  8) * HST + lcol);
            float4 h2 = *(const float4*)(Hs + (hrow + 16) * HST + lcol);
            float4 h3 = *(const float4*)(Hs + (hrow + 24) * HST + lcol);

            v0.x = fmaxf(v0.x + h0.x, 0.f); v0.y = fmaxf(v0.y + h0.y, 0.f);
            v0.z = fmaxf(v0.z + h0.z, 0.f); v0.w = fmaxf(v0.w + h0.w, 0.f);
            v1.x = fmaxf(v1.x + h1.x, 0.f); v1.y = fmaxf(v1.y + h1.y, 0.f);
            v1.z = fmaxf(v1.z + h1.z, 0.f); v1.w = fmaxf(v1.w + h1.w, 0.f);
            v2.x = fmaxf(v2.x + h2.x, 0.f); v2.y = fmaxf(v2.y + h2.y, 0.f);
            v2.z = fmaxf(v2.z + h2.z, 0.f); v2.w = fmaxf(v2.w + h2.w, 0.f);
            v3.x = fmaxf(v3.x + h3.x, 0.f); v3.y = fmaxf(v3.y + h3.y, 0.f);
            v3.z = fmaxf(v3.z + h3.z, 0.f); v3.w = fmaxf(v3.w + h3.w, 0.f);

            float4 cur = v0; int cd = d0;
            if (d1 == cd) {
                cur.x += v1.x; cur.y += v1.y; cur.z += v1.z; cur.w += v1.w;
            } else {
                red_add_v4(agg + (size_t)cd * 256 + col, cur);
                cur = v1; cd = d1;
            }
            if (d2 == cd) {
                cur.x += v2.x; cur.y += v2.y; cur.z += v2.z; cur.w += v2.w;
            } else {
                red_add_v4(agg + (size_t)cd * 256 + col, cur);
                cur = v2; cd = d2;
            }
            if (d3 == cd) {
                cur.x += v3.x; cur.y += v3.y; cur.z += v3.z; cur.w += v3.w;
            } else {
                red_add_v4(agg + (size_t)cd * 256 + col, cur);
                cur = v3; cd = d3;
            }
            red_add_v4(agg + (size_t)cd * 256 + col, cur);
        }
    }
}

// One block (64 threads) per node: scatter mean-pool contributions.
__global__ void pool_kernel(const float* __restrict__ h,
                            const int* __restrict__ batch,
                            float* __restrict__ pool, float* __restrict__ cnt)
{
    const int node = blockIdx.x;
    const int gph = batch[node];
    const int t = threadIdx.x;
    float4 v = *reinterpret_cast<const float4*>(h + (size_t)node * 256 + t * 4);
    red_add_v4(pool + (size_t)gph * 256 + t * 4, v);
    if (t == 0) atomicAdd(cnt + gph, 1.0f);
}

// One block per graph: mean -> relu(g@W1+b1)@W2+b2 -> L2 normalize.
__global__ void final_kernel(const float* __restrict__ pool,
                             const float* __restrict__ cnt,
                             const float* __restrict__ W1, const float* __restrict__ b1,
                             const float* __restrict__ W2, const float* __restrict__ b2,
                             float* __restrict__ out)
{
    const int gph = blockIdx.x;
    const int j = threadIdx.x;
    __shared__ float s[256];
    __shared__ float s2[256];
    __shared__ float redbuf[8];
    __shared__ float snorm;

    const float inv = 1.0f / fmaxf(cnt[gph], 1.0f);
    s[j] = pool[gph * 256 + j] * inv;
    __syncthreads();

    float t = b1[j];
    #pragma unroll 8
    for (int k = 0; k < 256; k++) t = fmaf(s[k], W1[k * 256 + j], t);
    t = fmaxf(t, 0.f);
    s2[j] = t;
    __syncthreads();

    float o = b2[j];
    #pragma unroll 8
    for (int k = 0; k < 256; k++) o = fmaf(s2[k], W2[k * 256 + j], o);

    float sq = o * o;
    #pragma unroll
    for (int off = 16; off > 0; off >>= 1)
        sq += __shfl_down_sync(0xffffffffu, sq, off);
    if ((j & 31) == 0) redbuf[j >> 5] = sq;
    __syncthreads();
    if (j == 0) {
        float ss = 0.f;
        #pragma unroll
        for (int w = 0; w < 8; w++) ss += redbuf[w];
        snorm = fmaxf(sqrtf(ss), 1e-12f);
    }
    __syncthreads();

    out[gph * 256 + j] = o / snorm;
}

extern "C" void kernel_launch(void* const* d_in, const int* in_sizes, int n_in,
                              void* d_out, int out_size)
{
    const float* x   = (const float*)d_in[0];
    const int*   ei  = (const int*)  d_in[1];
    const float* ea  = (const float*)d_in[2];
    const int*   bi  = (const int*)  d_in[3];
    const float* xW  = (const float*)d_in[4];
    const float* xb  = (const float*)d_in[5];
    const float* eW  = (const float*)d_in[6];
    const float* eb  = (const float*)d_in[7];
    const float* W1  = (const float*)d_in[8];
    const float* b1  = (const float*)d_in[9];
    const float* W2  = (const float*)d_in[10];
    const float* b2  = (const float*)d_in[11];
    const float* oW1 = (const float*)d_in[12];
    const float* ob1 = (const float*)d_in[13];
    const float* oW2 = (const float*)d_in[14];
    const float* ob2 = (const float*)d_in[15];
    float* out = (float*)d_out;

    float *ph, *pagg, *pt, *ppool, *pcnt;
    int *phisto, *pperm;
    cudaGetSymbolAddress((void**)&ph,    g_h);
    cudaGetSymbolAddress((void**)&pagg,  g_agg);
    cudaGetSymbolAddress((void**)&pt,    g_t);
    cudaGetSymbolAddress((void**)&ppool, g_pool);
    cudaGetSymbolAddress((void**)&pcnt,  g_cnt);
    cudaGetSymbolAddress((void**)&phisto, g_histo);
    cudaGetSymbolAddress((void**)&pperm,  g_perm);

    cudaFuncSetAttribute(mma_gemm<false, true>,
                         cudaFuncAttributeMaxDynamicSharedMemorySize, NSMEM_BYTES);
    cudaFuncSetAttribute(mma_gemm<true, false>,
                         cudaFuncAttributeMaxDynamicSharedMemorySize, NSMEM_BYTES);
    cudaFuncSetAttribute(mma_gemm<true, true>,
                         cudaFuncAttributeMaxDynamicSharedMemorySize, NSMEM_BYTES);
    cudaFuncSetAttribute(edge_gemm,
                         cudaFuncAttributeMaxDynamicSharedMemorySize, ESMEM_BYTES);

    dim3 gNode(2, (NN + 127) / 128);   // (2, 157)
    dim3 gEdge(2, NE / 128);           // (2, 2500)

    // ---- counting sort of edges by dst (histo zero via memset) ----
    cudaMemsetAsync(phisto, 0, NN * sizeof(int));
    hist_kernel<<<(NE + 255) / 256, 256>>>(ei, phisto);
    scan_kernel<<<1, 1024>>>(phisto);
    scatter_kernel<<<(NE + 255) / 256, 256>>>(ei, phisto, pperm);

    // pool/cnt zero via memset (overlaps with compute; only needed by pool_kernel)
    cudaMemsetAsync(ppool, 0, NG * 256 * sizeof(float));
    cudaMemsetAsync(pcnt, 0, NG * sizeof(float));

    // h = x @ xproj_W + xproj_b; agg = h (dual store)
    mma_gemm<false, true><<<gNode, 256, NSMEM_BYTES>>>(x, xW, xb, ph, pagg, NN, 128);

    for (int l = 0; l < 3; l++) {
        edge_gemm<<<gEdge, 256, ESMEM_BYTES>>>(
            ea, eW + l * 64 * 256, eb + l * 256, ei, pperm, ph, pagg);
        mma_gemm<true, false><<<gNode, 256, NSMEM_BYTES>>>(
            pagg, W1 + l * 256 * 256, b1 + l * 256, pt, nullptr, NN, 256);
        if (l < 2)
            mma_gemm<true, true><<<gNode, 256, NSMEM_BYTES>>>(
                pt, W2 + l * 256 * 256, b2 + l * 256, ph, pagg, NN, 256);
        else
            mma_gemm<true, false><<<gNode, 256, NSMEM_BYTES>>>(
                pt, W2 + l * 256 * 256, b2 + l * 256, ph, nullptr, NN, 256);
    }

    // mean pool
    pool_kernel<<<NN, 64>>>(ph, bi, ppool, pcnt);

    // graph head + normalize
    final_kernel<<<NG, 256>>>(ppool, pcnt, oW1, ob1, oW2, ob2, out);
}